// round 10
// baseline (speedup 1.0000x reference)
#include <cuda_runtime.h>
#include <math.h>

// Problem dims
#define Sd 32
#define Wd 64
#define Dd 256
#define Hd 256
#define Td (Sd*Wd)      // 2048
#define R4H 1024        // 4*H
#define Gn 16           // CTAs in recurrence (one 16-CTA cluster)
#define HSL (Hd/Gn)     // 16 hidden units per CTA
#define RECTHREADS 512
#define WORKERS 112     // co-resident workers (total 128 CTAs = 8 clusters)
#define NTBLK 16        // 2048 rows / 128-row blocks
#define NTILES 256      // 16 t-blocks x 16 r-tiles (128x64 tiles)

typedef unsigned long long ull;

// ---------------- device scratch (static, no allocation) ----------------
__device__ float g_Xp1[Td*R4H];        // 8 MB: W_ih1@x + b1 for all word steps
__device__ float g_Xp2[Sd*R4H];        // W_ih2@sentVec + b2
__device__ float g_Hwords[Td*Hd];      // all word-LSTM hiddens
__device__ float g_rowH[Sd*Hd];        // all sentence-LSTM hiddens
__device__ float g_sc1[Td];            // word attention exp-scores
__device__ float g_sc2[Sd];            // sentence attention exp-scores
__device__ float g_sentVec[Sd*Hd];
__device__ volatile int g_done[Gn];    // rec progress (steps done), reset by init
__device__ int g_gemm_cnt[NTBLK];      // completed r-tiles per 128-row t-block
__device__ int g_tile_next;            // work-stealing GEMM tile counter

// fast activations: single-MUFU tanh (sm_75+), sigmoid via tanh identity
__device__ __forceinline__ float ftanh(float x) {
    float y;
    asm("tanh.approx.f32 %0, %1;" : "=f"(y) : "f"(x));
    return y;
}
__device__ __forceinline__ float fsig(float x) {
    return fmaf(ftanh(0.5f * x), 0.5f, 0.5f);
}

// packed f32x2 helpers
__device__ __forceinline__ ull fma2(ull a, ull b, ull c) {
    ull d;
    asm("fma.rn.f32x2 %0, %1, %2, %3;" : "=l"(d) : "l"(a), "l"(b), "l"(c));
    return d;
}
__device__ __forceinline__ ull add2(ull a, ull b) {
    ull d;
    asm("add.rn.f32x2 %0, %1, %2;" : "=l"(d) : "l"(a), "l"(b));
    return d;
}

// cluster / mbarrier helpers
__device__ __forceinline__ unsigned smem_u32(const void* p) {
    return (unsigned)__cvta_generic_to_shared(p);
}
__device__ __forceinline__ unsigned mapa_u32(unsigned addr, unsigned rank) {
    unsigned r;
    asm("mapa.shared::cluster.u32 %0, %1, %2;" : "=r"(r) : "r"(addr), "r"(rank));
    return r;
}
__device__ __forceinline__ void st_async_b64(unsigned raddr, ull v, unsigned rmbar) {
    asm volatile(
        "st.async.shared::cluster.mbarrier::complete_tx::bytes.b64 [%0], %1, [%2];"
        :: "r"(raddr), "l"(v), "r"(rmbar) : "memory");
}
__device__ __forceinline__ void mbar_init(unsigned mbar, unsigned cnt) {
    asm volatile("mbarrier.init.shared.b64 [%0], %1;" :: "r"(mbar), "r"(cnt) : "memory");
}
__device__ __forceinline__ void mbar_expect_tx(unsigned mbar, unsigned bytes) {
    asm volatile("mbarrier.arrive.expect_tx.shared.b64 _, [%0], %1;"
                 :: "r"(mbar), "r"(bytes) : "memory");
}
__device__ __forceinline__ void mbar_wait_parity(unsigned mbar, unsigned parity) {
    asm volatile(
        "{\n\t"
        ".reg .pred P1;\n\t"
        "WAIT_%=:\n\t"
        "mbarrier.try_wait.parity.acquire.cluster.shared::cta.b64 P1, [%0], %1, 0x989680;\n\t"
        "@P1 bra DONE_%=;\n\t"
        "bra WAIT_%=;\n\t"
        "DONE_%=:\n\t"
        "}"
        :: "r"(mbar), "r"(parity) : "memory");
}

// convergent poll (warp0 lanes, broadcast address) for t-block readiness
__device__ __forceinline__ void wait_xp_block(int b) {
    while (((volatile int*)g_gemm_cnt)[b] < NTBLK) __nanosleep(64);
    __threadfence();
}

// =====================================================================
// K0: tiny init — reset progress flags & tile counters (replay safety)
// =====================================================================
__global__ void init_kernel()
{
    if (threadIdx.x < Gn)    ((int*)g_done)[threadIdx.x] = -1;
    if (threadIdx.x < NTBLK) g_gemm_cnt[threadIdx.x] = 0;
    if (threadIdx.x == 0)    g_tile_next = 0;
}

// =====================================================================
// K1: MEGA kernel.
//  CTAs 0..15   : word LSTM recurrence (16-CTA cluster, DSMEM push),
//                 xp prefetch gated on GEMM t-block counters.
//  CTAs 16..127 : workers — work-stealing GEMM tiles (tb-ascending,
//                 deadlock-free: any resident subset finishes), then
//                 word-attention tiles gated on rec progress (g_done).
// =====================================================================
__global__ void __launch_bounds__(RECTHREADS, 1) mega_kernel(
    const float* __restrict__ Whh, const float* __restrict__ h0,
    const float* __restrict__ c0, int nsteps, int which,
    const float* __restrict__ X, const float* __restrict__ Wih,
    const float* __restrict__ bias,
    const float* __restrict__ A1W, const float* __restrict__ A1B,
    const float* __restrict__ A1U)
{
    const int tid = threadIdx.x;

    if (blockIdx.x >= Gn) {
        // =================== worker path (which==0 only) ===================
        const int a = blockIdx.x - Gn;    // 0..111

        // ---- phase 1: work-stealing GEMM Xp1 = X @ Wih^T + bias ----
        // tile i: t-block tb = i>>4 (128 rows), r-tile = i&15 (64 cols).
        {
            __shared__ float As[128][33];
            __shared__ float Bs[64][33];
            __shared__ int s_tile;
            const int tx = tid & 15;      // r micro (4 cols)
            const int ty = tid >> 4;      // t micro (4 rows), 0..31
            for (;;) {
                __syncthreads();
                if (tid == 0) s_tile = atomicAdd(&g_tile_next, 1);
                __syncthreads();
                const int tile = s_tile;
                if (tile >= NTILES) break;
                const int tb = tile >> 4;
                const int t0 = tb * 128;
                const int r0 = (tile & 15) * 64;

                float acc[4][4];
#pragma unroll
                for (int i = 0; i < 4; i++)
#pragma unroll
                    for (int j = 0; j < 4; j++) acc[i][j] = 0.f;

                for (int kp = 0; kp < Dd; kp += 32) {
#pragma unroll
                    for (int p = 0; p < 2; p++) {
                        int idx = tid + p * 512;
                        int row = idx >> 3;
                        int c4  = (idx & 7) * 4;
                        float4 va = *(const float4*)&X[(size_t)(t0 + row) * Dd + kp + c4];
                        As[row][c4+0] = va.x; As[row][c4+1] = va.y;
                        As[row][c4+2] = va.z; As[row][c4+3] = va.w;
                    }
                    {
                        int row = tid >> 3;
                        int c4  = (tid & 7) * 4;
                        float4 vb = *(const float4*)&Wih[(size_t)(r0 + row) * Dd + kp + c4];
                        Bs[row][c4+0] = vb.x; Bs[row][c4+1] = vb.y;
                        Bs[row][c4+2] = vb.z; Bs[row][c4+3] = vb.w;
                    }
                    __syncthreads();
#pragma unroll
                    for (int k = 0; k < 32; k++) {
                        float av[4], bv[4];
#pragma unroll
                        for (int i = 0; i < 4; i++) av[i] = As[ty*4+i][k];
#pragma unroll
                        for (int j = 0; j < 4; j++) bv[j] = Bs[tx*4+j][k];
#pragma unroll
                        for (int i = 0; i < 4; i++)
#pragma unroll
                            for (int j = 0; j < 4; j++) acc[i][j] += av[i] * bv[j];
                    }
                    __syncthreads();
                }
                float4 bb = *(const float4*)&bias[r0 + tx*4];
#pragma unroll
                for (int i = 0; i < 4; i++) {
                    float4 o;
                    o.x = acc[i][0] + bb.x; o.y = acc[i][1] + bb.y;
                    o.z = acc[i][2] + bb.z; o.w = acc[i][3] + bb.w;
                    *(float4*)&g_Xp1[(size_t)(t0 + ty*4 + i) * R4H + r0 + tx*4] = o;
                }
                // publish: all stores visible, then count the tile
                __threadfence();
                __syncthreads();
                if (tid == 0) atomicAdd(&g_gemm_cnt[tb], 1);
            }
        }

        // ---- phase 2: word-attention tiles gated on rec progress ----
        {
            __shared__ float part[2][Hd];
            __shared__ float red[Hd];
            const int col  = tid & (Hd - 1);
            const int half = tid >> 8;      // 0/1 -> h rows [0,128)/[128,256)
            for (int sw = a; sw < Td; sw += WORKERS) {
                if (tid == 0) {
                    for (;;) {
                        int mn = g_done[0];
#pragma unroll
                        for (int g = 1; g < Gn; g++) {
                            int v = g_done[g];
                            mn = v < mn ? v : mn;
                        }
                        if (mn >= sw) break;
                        __nanosleep(256);
                    }
                }
                __syncthreads();

                const float* hwp = &g_Hwords[(size_t)sw * Hd + half * 128];
                const float* Wp  = A1W + (size_t)sw * Hd * Hd + (size_t)half * 128 * Hd;
                float acc = 0.f;
#pragma unroll 8
                for (int h = 0; h < 128; h++)
                    acc += __ldg(&hwp[h]) * __ldg(&Wp[(size_t)h * Hd + col]);
                part[half][col] = acc;
                __syncthreads();
                if (tid < Hd) {
                    float tot = part[0][tid] + part[1][tid];
                    float u = tanhf(tot + A1B[(size_t)sw * Hd + tid]);
                    red[tid] = u * A1U[(size_t)sw * Hd + tid];
                }
                __syncthreads();
                for (int off = 128; off > 0; off >>= 1) {
                    if (tid < off) red[tid] += red[tid + off];
                    __syncthreads();
                }
                if (tid == 0) g_sc1[sw] = expf(red[0]);
                __syncthreads();
            }
        }
        return;
    }

    // ===================== recurrence path (R8) =====================
    const float* xp   = which ? g_Xp2  : g_Xp1;
    float*       outH = which ? g_rowH : g_Hwords;
    const bool   gated = (which == 0);

    const int g    = blockIdx.x;          // == cluster rank
    const int cb   = tid >> 6;            // 0..7 column block (32 cols)
    const int r    = tid & 63;            // local gate row 0..63
    const int lane = tid & 31;
    const int grow  = (r >> 4) * Hd + g * HSL + (r & 15);
    const int growA = (lane >> 4) * Hd + g * HSL + (lane & 15);         // q=0/1
    const int growB = ((lane + 32) >> 4) * Hd + g * HSL + (lane & 15);  // q=2/3

    // preload weights as packed f32x2 (columns cb*32 .. +32)
    ull wreg[16];
#pragma unroll
    for (int j = 0; j < 16; j++)
        wreg[j] = *(const ull*)(Whh + (size_t)grow * Hd + cb * 32 + 2 * j);

    __shared__ __align__(16) float hbuf[2][Hd];
    __shared__ float psum[8][64];
    __shared__ __align__(8) ull s_mbar[2];

    if (tid < Hd) hbuf[0][tid] = h0[tid];
    float creg = 0.f;
    if (tid < HSL) creg = c0[g * HSL + tid];
    if (tid == 0) {
        mbar_init(smem_u32(&s_mbar[0]), 1);
        mbar_init(smem_u32(&s_mbar[1]), 1);
    }
    __syncthreads();
    asm volatile("barrier.cluster.arrive.aligned;" ::: "memory");
    asm volatile("barrier.cluster.wait.aligned;"   ::: "memory");

    const unsigned hb_u = smem_u32(&hbuf[0][0]);
    const unsigned mb_u = smem_u32(&s_mbar[0]);

    // b64 push mapping: lane sends pair k=(lane&7) (units 2k,2k+1) to
    // 4 peers: (lane>>3)*4 + 0..3
    unsigned rh4[4], rm4[4];
    const int kpair = lane & 7;
    if (tid < 32) {
#pragma unroll
        for (int p = 0; p < 4; p++) {
            unsigned peer = (unsigned)((lane >> 3) * 4 + p);
            rh4[p] = mapa_u32(hb_u, peer);
            rm4[p] = mapa_u32(mb_u, peer);
        }
    }

    // depth-2 xp prefetch; gate block 0 first when consuming live GEMM data
    float xpa = 0.f, xpb = 0.f, xpa1 = 0.f, xpb1 = 0.f;
    if (tid < 32) {
        if (gated) wait_xp_block(0);
        xpa = __ldg(&xp[growA]);
        xpb = __ldg(&xp[growB]);
        if (nsteps > 1) {
            xpa1 = __ldg(&xp[(size_t)R4H + growA]);
            xpb1 = __ldg(&xp[(size_t)R4H + growB]);
        }
    }

    for (int s = 0; s < nsteps; s++) {
        // issue prefetch for step s+2 (gated at 128-row block boundaries)
        float xpa2 = 0.f, xpb2 = 0.f;
        if (tid < 32 && s + 2 < nsteps) {
            const int row2 = s + 2;
            if (gated && (row2 & 127) == 0) wait_xp_block(row2 >> 7);
            xpa2 = __ldg(&xp[(size_t)row2 * R4H + growA]);
            xpb2 = __ldg(&xp[(size_t)row2 * R4H + growB]);
        }

        // matvec partials: 16 packed FMAs per thread
        const ull* hp = (const ull*)&hbuf[s & 1][cb * 32];
        ull a0 = 0ull, a1 = 0ull, a2 = 0ull, a3 = 0ull;
#pragma unroll
        for (int j = 0; j < 16; j += 4) {
            a0 = fma2(wreg[j+0], hp[j+0], a0);
            a1 = fma2(wreg[j+1], hp[j+1], a1);
            a2 = fma2(wreg[j+2], hp[j+2], a2);
            a3 = fma2(wreg[j+3], hp[j+3], a3);
        }
        ull at = add2(add2(a0, a1), add2(a2, a3));
        unsigned lo32, hi32;
        asm("mov.b64 {%0, %1}, %2;" : "=r"(lo32), "=r"(hi32) : "l"(at));
        psum[cb][r] = __uint_as_float(lo32) + __uint_as_float(hi32);
        __syncthreads();

        if (tid < 32) {
            float t1 = xpa, t2 = xpb;
#pragma unroll
            for (int c = 0; c < 8; c++) {
                t1 += psum[c][lane];
                t2 += psum[c][lane + 32];
            }
            // lanes 0..15: t1=i, t2=g ; lanes 16..31: t1=f, t2=o
            float fo1 = __shfl_xor_sync(0xffffffffu, t1, 16);
            float fo2 = __shfl_xor_sync(0xffffffffu, t2, 16);
            float hn = 0.f;
            if (lane < 16) {
                float ii = fsig(t1);
                float ff = fsig(fo1);
                float oo = fsig(fo2);
                creg = ff * creg + ii * ftanh(t2);
                hn = oo * ftanh(creg);
            }
            if (s + 1 < nsteps) {
                // gather pair (2k, 2k+1) and push as one b64 to 4 peers
                float hlo = __shfl_sync(0xffffffffu, hn, 2 * kpair);
                float hhi = __shfl_sync(0xffffffffu, hn, 2 * kpair + 1);
                ull pv;
                asm("mov.b64 %0, {%1, %2};" : "=l"(pv)
                    : "r"(__float_as_uint(hlo)), "r"(__float_as_uint(hhi)));
                const int nb = (s + 1) & 1;
                if (lane == 0) mbar_expect_tx(mb_u + nb * 8, Hd * 4);
                unsigned off = (unsigned)((nb * Hd + g * HSL + 2 * kpair) * 4);
#pragma unroll
                for (int p = 0; p < 4; p++)
                    st_async_b64(rh4[p] + off, pv, rm4[p] + nb * 8);
            }
            if (lane < 16)
                outH[(size_t)s * Hd + g * HSL + lane] = hn;
            // publish rec progress for attention workers
            if (which == 0 && lane == 0 && (s & 63) == 63) {
                __threadfence();
                g_done[g] = s;
            }
        }
        xpa = xpa1; xpb = xpb1;
        xpa1 = xpa2; xpb1 = xpb2;

        if (s + 1 < nsteps) {
            mbar_wait_parity(mb_u + ((s + 1) & 1) * 8, (unsigned)((s >> 1) & 1));
        }
    }

    asm volatile("barrier.cluster.arrive.aligned;" ::: "memory");
    asm volatile("barrier.cluster.wait.aligned;"   ::: "memory");
}

// =====================================================================
// K3: per-sentence softmax + sentVec (coalesced over h)
// =====================================================================
__global__ void __launch_bounds__(256) sentvec_kernel()
{
    const int s = blockIdx.x;
    const int tid = threadIdx.x;
    __shared__ float sc[Wd];
    __shared__ float ssum_s;
    if (tid < Wd) sc[tid] = g_sc1[s * Wd + tid];
    __syncthreads();
    if (tid == 0) {
        float t = 0.f;
        for (int w = 0; w < Wd; w++) t += sc[w];
        ssum_s = t;
    }
    __syncthreads();
    float acc = 0.f;
#pragma unroll 8
    for (int w = 0; w < Wd; w++)
        acc += g_Hwords[(size_t)(s * Wd + w) * Hd + tid] * sc[w];
    g_sentVec[s * Hd + tid] = acc / ssum_s;
}

// =====================================================================
// K4: Xp2 = W_ih2 @ sentVec + b2, warp-per-row coalesced
// =====================================================================
__global__ void __launch_bounds__(256) xp2_kernel(
    const float* __restrict__ W_ih2, const float* __restrict__ b2)
{
    const int s  = blockIdx.x;
    const int rb = blockIdx.y;
    const int tid = threadIdx.x;
    const int w   = tid >> 5;
    const int lane = tid & 31;
    __shared__ float svs[Hd];
    if (tid < Hd) svs[tid] = g_sentVec[s * Hd + tid];
    __syncthreads();

#pragma unroll
    for (int i = 0; i < 32; i++) {
        int row = rb * 256 + w * 32 + i;
        const float* wp = W_ih2 + (size_t)row * Hd;
        float a = 0.f;
#pragma unroll
        for (int d = 0; d < 8; d++)
            a += __ldg(&wp[lane + d * 32]) * svs[lane + d * 32];
#pragma unroll
        for (int off = 16; off > 0; off >>= 1)
            a += __shfl_xor_sync(0xffffffffu, a, off);
        if (lane == 0) g_Xp2[s * R4H + row] = a + b2[row];
    }
}

// =====================================================================
// K6: sentence attention scores (stale last word hidden, per reference)
// =====================================================================
__global__ void __launch_bounds__(256) sent_attn_kernel(
    const float* __restrict__ A2W, const float* __restrict__ A2B,
    const float* __restrict__ A2U)
{
    const int s = blockIdx.x;
    const int tid = threadIdx.x;
    __shared__ float lastv[Hd];
    __shared__ float red[256];
    lastv[tid] = g_Hwords[(size_t)(Td - 1) * Hd + tid];
    __syncthreads();
    const float* Wp = A2W + (size_t)s * Hd * Hd;
    float acc = 0.f;
#pragma unroll 8
    for (int h = 0; h < Hd; h++) acc += lastv[h] * __ldg(&Wp[(size_t)h * Hd + tid]);
    float u = tanhf(acc + A2B[s * Hd + tid]);
    float p = u * A2U[s * Hd + tid];
    red[tid] = p;
    __syncthreads();
    for (int off = 128; off > 0; off >>= 1) {
        if (tid < off) red[tid] += red[tid + off];
        __syncthreads();
    }
    if (tid == 0) g_sc2[s] = expf(red[0]);
}

// =====================================================================
// K7: final: out = sigmoid( (rowH^T softmax(sc2)) . Wf + bf )
// =====================================================================
__global__ void __launch_bounds__(256) final_kernel(
    const float* __restrict__ Wf, const float* __restrict__ bf,
    float* __restrict__ out)
{
    const int tid = threadIdx.x;
    __shared__ float sc[Sd];
    __shared__ float red[256];
    if (tid < Sd) sc[tid] = g_sc2[tid];
    __syncthreads();
    float ssum = 0.f;
#pragma unroll
    for (int s = 0; s < Sd; s++) ssum += sc[s];
    float acc = 0.f;
#pragma unroll
    for (int s = 0; s < Sd; s++) acc += g_rowH[s * Hd + tid] * sc[s];
    float o2 = acc / ssum;
    red[tid] = o2 * Wf[tid];
    __syncthreads();
    for (int off = 128; off > 0; off >>= 1) {
        if (tid < off) red[tid] += red[tid + off];
        __syncthreads();
    }
    if (tid == 0) out[0] = 1.f / (1.f + expf(-(red[0] + bf[0])));
}

// =====================================================================
extern "C" void kernel_launch(void* const* d_in, const int* in_sizes, int n_in,
                              void* d_out, int out_size)
{
    const float* inputs = (const float*)d_in[0];
    const float* W_ih1  = (const float*)d_in[1];
    const float* W_hh1  = (const float*)d_in[2];
    const float* b1     = (const float*)d_in[3];
    const float* W_ih2  = (const float*)d_in[4];
    const float* W_hh2  = (const float*)d_in[5];
    const float* b2     = (const float*)d_in[6];
    const float* h1_0   = (const float*)d_in[7];
    const float* c1_0   = (const float*)d_in[8];
    const float* h2_0   = (const float*)d_in[9];
    const float* c2_0   = (const float*)d_in[10];
    const float* A1W    = (const float*)d_in[11];
    const float* A1B    = (const float*)d_in[12];
    const float* A1U    = (const float*)d_in[13];
    const float* A2W    = (const float*)d_in[14];
    const float* A2B    = (const float*)d_in[15];
    const float* A2U    = (const float*)d_in[16];
    const float* Wf     = (const float*)d_in[17];
    const float* bf     = (const float*)d_in[18];
    float* out = (float*)d_out;

    // allow 16-CTA (non-portable) cluster for the mega kernel
    cudaFuncSetAttribute((const void*)mega_kernel,
                         cudaFuncAttributeNonPortableClusterSizeAllowed, 1);

    // K0: reset progress flags / tile counters
    init_kernel<<<1, 32>>>();

    // K1: mega kernel — rec cluster + 112 workers (128 CTAs = 8 clusters,
    // the co-residency shape proven in R8)
    cudaLaunchConfig_t cfg = {};
    cfg.gridDim  = dim3(Gn + WORKERS, 1, 1);
    cfg.blockDim = dim3(RECTHREADS, 1, 1);
    cfg.dynamicSmemBytes = 0;
    cfg.stream = 0;
    cudaLaunchAttribute attrs[1];
    attrs[0].id = cudaLaunchAttributeClusterDimension;
    attrs[0].val.clusterDim.x = Gn;
    attrs[0].val.clusterDim.y = 1;
    attrs[0].val.clusterDim.z = 1;
    cfg.attrs = attrs;
    cfg.numAttrs = 1;
    cudaLaunchKernelEx(&cfg, mega_kernel, W_hh1, h1_0, c1_0, (int)Td, 0,
                       inputs, W_ih1, b1, A1W, A1B, A1U);

    // K3: sentence vectors
    sentvec_kernel<<<Sd, 256>>>();

    // K4: sentence-LSTM input projection
    dim3 g4(Sd, 4);
    xp2_kernel<<<g4, 256>>>(W_ih2, b2);

    // K5: sentence-level recurrence (32 steps, rec cluster only)
    cudaLaunchConfig_t cfg5 = cfg;
    cfg5.gridDim = dim3(Gn, 1, 1);
    cudaLaunchKernelEx(&cfg5, mega_kernel, W_hh2, h2_0, c2_0, (int)Sd, 1,
                       inputs, W_ih1, b1, A1W, A1B, A1U);

    // K6: sentence attention scores
    sent_attn_kernel<<<Sd, 256>>>(A2W, A2B, A2U);

    // K7: final output
    final_kernel<<<1, 256>>>(Wf, bf, out);
}

// round 11
// speedup vs baseline: 1.1971x; 1.1971x over previous
#include <cuda_runtime.h>
#include <math.h>

// Problem dims
#define Sd 32
#define Wd 64
#define Dd 256
#define Hd 256
#define Td (Sd*Wd)      // 2048
#define R4H 1024        // 4*H
#define Gn 16           // CTAs in recurrence (one 16-CTA cluster)
#define HSL (Hd/Gn)     // 16 hidden units per CTA
#define RECTHREADS 512
#define ATTN_CTAS 96    // co-resident word-attention CTAs (R8 shape)

typedef unsigned long long ull;

// ---------------- device scratch (static, no allocation) ----------------
__device__ float g_Xp1[Td*R4H];        // 8 MB: W_ih1@x + b1 for all word steps
__device__ float g_Xp2[Sd*R4H];        // W_ih2@sentVec + b2
__device__ float g_Hwords[Td*Hd];      // all word-LSTM hiddens
__device__ float g_rowH[Sd*Hd];        // all sentence-LSTM hiddens
__device__ float g_sc1[Td];            // word attention exp-scores
__device__ float g_sc2[Sd];            // sentence attention exp-scores
__device__ float g_sentVec[Sd*Hd];
__device__ volatile int g_done[Gn];    // per-CTA rec progress; reset by K0
__device__ int g_s2cnt;                // sent_attn completion counter; reset by K0

// fast activations: single-MUFU tanh (sm_75+), sigmoid via tanh identity
__device__ __forceinline__ float ftanh(float x) {
    float y;
    asm("tanh.approx.f32 %0, %1;" : "=f"(y) : "f"(x));
    return y;
}
__device__ __forceinline__ float fsig(float x) {
    return fmaf(ftanh(0.5f * x), 0.5f, 0.5f);
}

// packed f32x2 helpers
__device__ __forceinline__ ull fma2(ull a, ull b, ull c) {
    ull d;
    asm("fma.rn.f32x2 %0, %1, %2, %3;" : "=l"(d) : "l"(a), "l"(b), "l"(c));
    return d;
}
__device__ __forceinline__ ull add2(ull a, ull b) {
    ull d;
    asm("add.rn.f32x2 %0, %1, %2;" : "=l"(d) : "l"(a), "l"(b));
    return d;
}

// cluster / mbarrier helpers
__device__ __forceinline__ unsigned smem_u32(const void* p) {
    return (unsigned)__cvta_generic_to_shared(p);
}
__device__ __forceinline__ unsigned mapa_u32(unsigned addr, unsigned rank) {
    unsigned r;
    asm("mapa.shared::cluster.u32 %0, %1, %2;" : "=r"(r) : "r"(addr), "r"(rank));
    return r;
}
__device__ __forceinline__ void st_async_b64(unsigned raddr, ull v, unsigned rmbar) {
    asm volatile(
        "st.async.shared::cluster.mbarrier::complete_tx::bytes.b64 [%0], %1, [%2];"
        :: "r"(raddr), "l"(v), "r"(rmbar) : "memory");
}
__device__ __forceinline__ void mbar_init(unsigned mbar, unsigned cnt) {
    asm volatile("mbarrier.init.shared.b64 [%0], %1;" :: "r"(mbar), "r"(cnt) : "memory");
}
__device__ __forceinline__ void mbar_expect_tx(unsigned mbar, unsigned bytes) {
    asm volatile("mbarrier.arrive.expect_tx.shared.b64 _, [%0], %1;"
                 :: "r"(mbar), "r"(bytes) : "memory");
}
__device__ __forceinline__ void mbar_wait_parity(unsigned mbar, unsigned parity) {
    asm volatile(
        "{\n\t"
        ".reg .pred P1;\n\t"
        "WAIT_%=:\n\t"
        "mbarrier.try_wait.parity.acquire.cluster.shared::cta.b64 P1, [%0], %1, 0x989680;\n\t"
        "@P1 bra DONE_%=;\n\t"
        "bra WAIT_%=;\n\t"
        "DONE_%=:\n\t"
        "}"
        :: "r"(mbar), "r"(parity) : "memory");
}

// =====================================================================
// K0: Xp1 = inputs(2048x256) @ W_ih1^T(1024x256) + b1   (NT GEMM)
//     block(0,0) also resets g_done + g_s2cnt (graph-replay safety).
// =====================================================================
__global__ void __launch_bounds__(256) gemm_xp1_kernel(
    const float* __restrict__ X, const float* __restrict__ Wm,
    const float* __restrict__ bias)
{
    if (blockIdx.x == 0 && blockIdx.y == 0) {
        if (threadIdx.x < Gn) ((int*)g_done)[threadIdx.x] = -1;
        if (threadIdx.x == Gn) g_s2cnt = 0;
    }

    __shared__ float As[128][33];
    __shared__ float Bs[64][33];
    const int tid = threadIdx.x;
    const int r0 = blockIdx.x * 64;
    const int t0 = blockIdx.y * 128;
    const int tx = tid & 15;   // r micro (4 cols)
    const int ty = tid >> 4;   // t micro (8 rows)

    float acc[8][4];
#pragma unroll
    for (int i = 0; i < 8; i++)
#pragma unroll
        for (int j = 0; j < 4; j++) acc[i][j] = 0.f;

    for (int kp = 0; kp < Dd; kp += 32) {
#pragma unroll
        for (int p = 0; p < 4; p++) {
            int idx = tid + p * 256;
            int row = idx >> 3;
            int c4  = (idx & 7) * 4;
            float4 va = *(const float4*)&X[(size_t)(t0 + row) * Dd + kp + c4];
            As[row][c4+0] = va.x; As[row][c4+1] = va.y;
            As[row][c4+2] = va.z; As[row][c4+3] = va.w;
        }
#pragma unroll
        for (int p = 0; p < 2; p++) {
            int idx = tid + p * 256;
            int row = idx >> 3;
            int c4  = (idx & 7) * 4;
            float4 vb = *(const float4*)&Wm[(size_t)(r0 + row) * Dd + kp + c4];
            Bs[row][c4+0] = vb.x; Bs[row][c4+1] = vb.y;
            Bs[row][c4+2] = vb.z; Bs[row][c4+3] = vb.w;
        }
        __syncthreads();
#pragma unroll
        for (int k = 0; k < 32; k++) {
            float a[8], b[4];
#pragma unroll
            for (int i = 0; i < 8; i++) a[i] = As[ty*8+i][k];
#pragma unroll
            for (int j = 0; j < 4; j++) b[j] = Bs[tx*4+j][k];
#pragma unroll
            for (int i = 0; i < 8; i++)
#pragma unroll
                for (int j = 0; j < 4; j++) acc[i][j] += a[i] * b[j];
        }
        __syncthreads();
    }
    float4 bv = *(const float4*)&bias[r0 + tx*4];
#pragma unroll
    for (int i = 0; i < 8; i++) {
        float4 o;
        o.x = acc[i][0] + bv.x; o.y = acc[i][1] + bv.y;
        o.z = acc[i][2] + bv.z; o.w = acc[i][3] + bv.w;
        *(float4*)&g_Xp1[(size_t)(t0 + ty*8 + i) * R4H + r0 + tx*4] = o;
    }
}

// =====================================================================
// K1/K5: recurrence (R8, cluster 0) + co-resident word attention
// (CTAs 16..111) consuming Hwords behind published progress.
// =====================================================================
__global__ void __launch_bounds__(RECTHREADS, 1) lstm_rec_kernel(
    const float* __restrict__ Whh, const float* __restrict__ h0,
    const float* __restrict__ c0, int nsteps, int which,
    const float* __restrict__ A1W, const float* __restrict__ A1B,
    const float* __restrict__ A1U)
{
    const int tid = threadIdx.x;

    if (blockIdx.x >= Gn) {
        // ============== word-attention path (which==0 launches only) ====
        __shared__ float part[2][Hd];
        __shared__ float red[Hd];
        const int a    = blockIdx.x - Gn;
        const int col  = tid & (Hd - 1);
        const int half = tid >> 8;          // 0/1 -> h rows [0,128)/[128,256)
        for (int sw = a; sw < Td; sw += ATTN_CTAS) {
            if (tid == 0) {
                for (;;) {
                    int mn = g_done[0];
#pragma unroll
                    for (int g = 1; g < Gn; g++) {
                        int v = g_done[g];
                        mn = v < mn ? v : mn;
                    }
                    if (mn >= sw) break;
                    __nanosleep(256);
                }
            }
            __syncthreads();

            const float* hwp = &g_Hwords[(size_t)sw * Hd + half * 128];
            const float* Wp  = A1W + (size_t)sw * Hd * Hd + (size_t)half * 128 * Hd;
            float acc = 0.f;
#pragma unroll 8
            for (int h = 0; h < 128; h++)
                acc += __ldg(&hwp[h]) * __ldg(&Wp[(size_t)h * Hd + col]);
            part[half][col] = acc;
            __syncthreads();
            if (tid < Hd) {
                float tot = part[0][tid] + part[1][tid];
                float u = tanhf(tot + A1B[(size_t)sw * Hd + tid]);
                red[tid] = u * A1U[(size_t)sw * Hd + tid];
            }
            __syncthreads();
            for (int off = 128; off > 0; off >>= 1) {
                if (tid < off) red[tid] += red[tid + off];
                __syncthreads();
            }
            if (tid == 0) g_sc1[sw] = expf(red[0]);
            __syncthreads();
        }
        return;
    }

    // ===================== recurrence path (R8) =====================
    const float* xp   = which ? g_Xp2  : g_Xp1;
    float*       outH = which ? g_rowH : g_Hwords;

    const int g    = blockIdx.x;          // == cluster rank
    const int cb   = tid >> 6;            // 0..7 column block (32 cols)
    const int r    = tid & 63;            // local gate row 0..63
    const int lane = tid & 31;
    const int grow  = (r >> 4) * Hd + g * HSL + (r & 15);
    const int growA = (lane >> 4) * Hd + g * HSL + (lane & 15);         // q=0/1
    const int growB = ((lane + 32) >> 4) * Hd + g * HSL + (lane & 15);  // q=2/3

    // preload weights as packed f32x2 (columns cb*32 .. +32)
    ull wreg[16];
#pragma unroll
    for (int j = 0; j < 16; j++)
        wreg[j] = *(const ull*)(Whh + (size_t)grow * Hd + cb * 32 + 2 * j);

    __shared__ __align__(16) float hbuf[2][Hd];
    __shared__ float psum[8][64];
    __shared__ __align__(8) ull s_mbar[2];

    if (tid < Hd) hbuf[0][tid] = h0[tid];
    float creg = 0.f;
    if (tid < HSL) creg = c0[g * HSL + tid];
    if (tid == 0) {
        mbar_init(smem_u32(&s_mbar[0]), 1);
        mbar_init(smem_u32(&s_mbar[1]), 1);
    }
    __syncthreads();
    asm volatile("barrier.cluster.arrive.aligned;" ::: "memory");
    asm volatile("barrier.cluster.wait.aligned;"   ::: "memory");

    const unsigned hb_u = smem_u32(&hbuf[0][0]);
    const unsigned mb_u = smem_u32(&s_mbar[0]);

    // b64 push mapping: lane sends pair k=(lane&7) (units 2k,2k+1) to
    // 4 peers: (lane>>3)*4 + 0..3
    unsigned rh4[4], rm4[4];
    const int kpair = lane & 7;
    if (tid < 32) {
#pragma unroll
        for (int p = 0; p < 4; p++) {
            unsigned peer = (unsigned)((lane >> 3) * 4 + p);
            rh4[p] = mapa_u32(hb_u, peer);
            rm4[p] = mapa_u32(mb_u, peer);
        }
    }

    // depth-2 xp prefetch (two full steps of latency cover)
    float xpa = 0.f, xpb = 0.f, xpa1 = 0.f, xpb1 = 0.f;
    if (tid < 32) {
        xpa = __ldg(&xp[growA]);
        xpb = __ldg(&xp[growB]);
        if (nsteps > 1) {
            xpa1 = __ldg(&xp[(size_t)R4H + growA]);
            xpb1 = __ldg(&xp[(size_t)R4H + growB]);
        }
    }

    for (int s = 0; s < nsteps; s++) {
        // issue prefetch for step s+2
        float xpa2 = 0.f, xpb2 = 0.f;
        if (tid < 32 && s + 2 < nsteps) {
            xpa2 = __ldg(&xp[(size_t)(s + 2) * R4H + growA]);
            xpb2 = __ldg(&xp[(size_t)(s + 2) * R4H + growB]);
        }

        // matvec partials: 16 packed FMAs per thread
        const ull* hp = (const ull*)&hbuf[s & 1][cb * 32];
        ull a0 = 0ull, a1 = 0ull, a2 = 0ull, a3 = 0ull;
#pragma unroll
        for (int j = 0; j < 16; j += 4) {
            a0 = fma2(wreg[j+0], hp[j+0], a0);
            a1 = fma2(wreg[j+1], hp[j+1], a1);
            a2 = fma2(wreg[j+2], hp[j+2], a2);
            a3 = fma2(wreg[j+3], hp[j+3], a3);
        }
        ull at = add2(add2(a0, a1), add2(a2, a3));
        unsigned lo32, hi32;
        asm("mov.b64 {%0, %1}, %2;" : "=r"(lo32), "=r"(hi32) : "l"(at));
        psum[cb][r] = __uint_as_float(lo32) + __uint_as_float(hi32);
        __syncthreads();

        if (tid < 32) {
            float t1 = xpa, t2 = xpb;
#pragma unroll
            for (int c = 0; c < 8; c++) {
                t1 += psum[c][lane];
                t2 += psum[c][lane + 32];
            }
            // lanes 0..15: t1=i, t2=g ; lanes 16..31: t1=f, t2=o
            float fo1 = __shfl_xor_sync(0xffffffffu, t1, 16);
            float fo2 = __shfl_xor_sync(0xffffffffu, t2, 16);
            float hn = 0.f;
            if (lane < 16) {
                float ii = fsig(t1);
                float ff = fsig(fo1);
                float oo = fsig(fo2);
                creg = ff * creg + ii * ftanh(t2);
                hn = oo * ftanh(creg);
            }
            if (s + 1 < nsteps) {
                // gather pair (2k, 2k+1) and push as one b64 to 4 peers
                float hlo = __shfl_sync(0xffffffffu, hn, 2 * kpair);
                float hhi = __shfl_sync(0xffffffffu, hn, 2 * kpair + 1);
                ull pv;
                asm("mov.b64 %0, {%1, %2};" : "=l"(pv)
                    : "r"(__float_as_uint(hlo)), "r"(__float_as_uint(hhi)));
                const int nb = (s + 1) & 1;
                if (lane == 0) mbar_expect_tx(mb_u + nb * 8, Hd * 4);
                unsigned off = (unsigned)((nb * Hd + g * HSL + 2 * kpair) * 4);
#pragma unroll
                for (int p = 0; p < 4; p++)
                    st_async_b64(rh4[p] + off, pv, rm4[p] + nb * 8);
            }
            if (lane < 16)
                outH[(size_t)s * Hd + g * HSL + lane] = hn;
            // publish rec progress for attention workers
            if (which == 0 && lane == 0 && (s & 63) == 63) {
                __threadfence();
                g_done[g] = s;
            }
        }
        xpa = xpa1; xpb = xpb1;
        xpa1 = xpa2; xpb1 = xpb2;

        if (s + 1 < nsteps) {
            mbar_wait_parity(mb_u + ((s + 1) & 1) * 8, (unsigned)((s >> 1) & 1));
        }
    }

    asm volatile("barrier.cluster.arrive.aligned;" ::: "memory");
    asm volatile("barrier.cluster.wait.aligned;"   ::: "memory");
}

// =====================================================================
// K3: per-sentence softmax + sentVec (coalesced over h)
// =====================================================================
__global__ void __launch_bounds__(256) sentvec_kernel()
{
    const int s = blockIdx.x;
    const int tid = threadIdx.x;
    __shared__ float sc[Wd];
    __shared__ float ssum_s;
    if (tid < Wd) sc[tid] = g_sc1[s * Wd + tid];
    __syncthreads();
    if (tid == 0) {
        float t = 0.f;
        for (int w = 0; w < Wd; w++) t += sc[w];
        ssum_s = t;
    }
    __syncthreads();
    float acc = 0.f;
#pragma unroll 8
    for (int w = 0; w < Wd; w++)
        acc += g_Hwords[(size_t)(s * Wd + w) * Hd + tid] * sc[w];
    g_sentVec[s * Hd + tid] = acc / ssum_s;
}

// =====================================================================
// K4: Xp2 = sentVec(32x256) @ W_ih2^T(1024x256) + b2  — NT GEMM tiles
// grid: 8 blocks of 256 threads; tile 32(t) x 128(r); micro 4x4.
// Replaces the shuffle-serial warp-per-row version (22.6us -> ~6us).
// =====================================================================
__global__ void __launch_bounds__(256) xp2_gemm_kernel(
    const float* __restrict__ W_ih2, const float* __restrict__ b2)
{
    __shared__ float As[32][33];     // sentVec panel
    __shared__ float Bs[128][33];    // W_ih2 panel
    const int tid = threadIdx.x;
    const int r0 = blockIdx.x * 128;
    const int tx = tid & 31;   // r micro (4 cols over 128)
    const int ty = tid >> 5;   // t micro (4 rows over 32)

    float acc[4][4];
#pragma unroll
    for (int i = 0; i < 4; i++)
#pragma unroll
        for (int j = 0; j < 4; j++) acc[i][j] = 0.f;

    for (int kp = 0; kp < Hd; kp += 32) {
        {
            int row = tid >> 3;
            int c4  = (tid & 7) * 4;
            float4 va = *(const float4*)&g_sentVec[(size_t)row * Hd + kp + c4];
            As[row][c4+0] = va.x; As[row][c4+1] = va.y;
            As[row][c4+2] = va.z; As[row][c4+3] = va.w;
        }
#pragma unroll
        for (int p = 0; p < 4; p++) {
            int idx = tid + p * 256;
            int row = idx >> 3;
            int c4  = (idx & 7) * 4;
            float4 vb = *(const float4*)&W_ih2[(size_t)(r0 + row) * Hd + kp + c4];
            Bs[row][c4+0] = vb.x; Bs[row][c4+1] = vb.y;
            Bs[row][c4+2] = vb.z; Bs[row][c4+3] = vb.w;
        }
        __syncthreads();
#pragma unroll
        for (int k = 0; k < 32; k++) {
            float a[4], b[4];
#pragma unroll
            for (int i = 0; i < 4; i++) a[i] = As[ty*4+i][k];
#pragma unroll
            for (int j = 0; j < 4; j++) b[j] = Bs[tx*4+j][k];
#pragma unroll
            for (int i = 0; i < 4; i++)
#pragma unroll
                for (int j = 0; j < 4; j++) acc[i][j] += a[i] * b[j];
        }
        __syncthreads();
    }
    float4 bb = *(const float4*)&b2[r0 + tx*4];
#pragma unroll
    for (int i = 0; i < 4; i++) {
        float4 o;
        o.x = acc[i][0] + bb.x; o.y = acc[i][1] + bb.y;
        o.z = acc[i][2] + bb.z; o.w = acc[i][3] + bb.w;
        *(float4*)&g_Xp2[(size_t)(ty*4 + i) * R4H + r0 + tx*4] = o;
    }
}

// =====================================================================
// K6: sentence attention scores + fused final (last CTA does the
// softmax-weighted rowH reduction and sigmoid output).
// =====================================================================
__global__ void __launch_bounds__(256) sent_attn_final_kernel(
    const float* __restrict__ A2W, const float* __restrict__ A2B,
    const float* __restrict__ A2U,
    const float* __restrict__ Wf, const float* __restrict__ bf,
    float* __restrict__ out)
{
    const int s = blockIdx.x;
    const int tid = threadIdx.x;
    __shared__ float lastv[Hd];
    __shared__ float red[256];
    __shared__ int s_last;
    lastv[tid] = g_Hwords[(size_t)(Td - 1) * Hd + tid];
    __syncthreads();
    const float* Wp = A2W + (size_t)s * Hd * Hd;
    float acc = 0.f;
#pragma unroll 8
    for (int h = 0; h < Hd; h++) acc += lastv[h] * __ldg(&Wp[(size_t)h * Hd + tid]);
    float u = tanhf(acc + A2B[s * Hd + tid]);
    float p = u * A2U[s * Hd + tid];
    red[tid] = p;
    __syncthreads();
    for (int off = 128; off > 0; off >>= 1) {
        if (tid < off) red[tid] += red[tid + off];
        __syncthreads();
    }
    if (tid == 0) {
        g_sc2[s] = expf(red[0]);
        __threadfence();
        s_last = (atomicAdd(&g_s2cnt, 1) == Sd - 1);
    }
    __syncthreads();
    if (!s_last) return;

    // -------- final: out = sigmoid((rowH^T softmax(sc2)) . Wf + bf) ----
    __threadfence();
    __shared__ float sc[Sd];
    if (tid < Sd) sc[tid] = *((volatile float*)&g_sc2[tid]);
    __syncthreads();
    float ssum = 0.f;
#pragma unroll
    for (int k = 0; k < Sd; k++) ssum += sc[k];
    float a2 = 0.f;
#pragma unroll
    for (int k = 0; k < Sd; k++) a2 += g_rowH[k * Hd + tid] * sc[k];
    float o2 = a2 / ssum;
    red[tid] = o2 * Wf[tid];
    __syncthreads();
    for (int off = 128; off > 0; off >>= 1) {
        if (tid < off) red[tid] += red[tid + off];
        __syncthreads();
    }
    if (tid == 0) out[0] = 1.f / (1.f + expf(-(red[0] + bf[0])));
}

// =====================================================================
extern "C" void kernel_launch(void* const* d_in, const int* in_sizes, int n_in,
                              void* d_out, int out_size)
{
    const float* inputs = (const float*)d_in[0];
    const float* W_ih1  = (const float*)d_in[1];
    const float* W_hh1  = (const float*)d_in[2];
    const float* b1     = (const float*)d_in[3];
    const float* W_ih2  = (const float*)d_in[4];
    const float* W_hh2  = (const float*)d_in[5];
    const float* b2     = (const float*)d_in[6];
    const float* h1_0   = (const float*)d_in[7];
    const float* c1_0   = (const float*)d_in[8];
    const float* h2_0   = (const float*)d_in[9];
    const float* c2_0   = (const float*)d_in[10];
    const float* A1W    = (const float*)d_in[11];
    const float* A1B    = (const float*)d_in[12];
    const float* A1U    = (const float*)d_in[13];
    const float* A2W    = (const float*)d_in[14];
    const float* A2B    = (const float*)d_in[15];
    const float* A2U    = (const float*)d_in[16];
    const float* Wf     = (const float*)d_in[17];
    const float* bf     = (const float*)d_in[18];
    float* out = (float*)d_out;

    // allow 16-CTA (non-portable) cluster for the recurrence kernel
    cudaFuncSetAttribute((const void*)lstm_rec_kernel,
                         cudaFuncAttributeNonPortableClusterSizeAllowed, 1);

    // K0: input projection GEMM for word LSTM (+ reset g_done / g_s2cnt)
    dim3 g0(R4H / 64, Td / 128);
    gemm_xp1_kernel<<<g0, 256>>>(inputs, W_ih1, b1);

    // K1: word recurrence (cluster 0) + co-resident word attention
    cudaLaunchConfig_t cfg = {};
    cfg.gridDim  = dim3(Gn + ATTN_CTAS, 1, 1);   // 112 CTAs, 7 clusters of 16
    cfg.blockDim = dim3(RECTHREADS, 1, 1);
    cfg.dynamicSmemBytes = 0;
    cfg.stream = 0;
    cudaLaunchAttribute attrs[1];
    attrs[0].id = cudaLaunchAttributeClusterDimension;
    attrs[0].val.clusterDim.x = Gn;
    attrs[0].val.clusterDim.y = 1;
    attrs[0].val.clusterDim.z = 1;
    cfg.attrs = attrs;
    cfg.numAttrs = 1;
    cudaLaunchKernelEx(&cfg, lstm_rec_kernel, W_hh1, h1_0, c1_0, (int)Td, 0,
                       A1W, A1B, A1U);

    // K3: sentence vectors
    sentvec_kernel<<<Sd, 256>>>();

    // K4: sentence-LSTM input projection (GEMM tiles)
    xp2_gemm_kernel<<<8, 256>>>(W_ih2, b2);

    // K5: sentence-level recurrence (32 steps, rec cluster only)
    cudaLaunchConfig_t cfg5 = cfg;
    cfg5.gridDim = dim3(Gn, 1, 1);
    cudaLaunchKernelEx(&cfg5, lstm_rec_kernel, W_hh2, h2_0, c2_0, (int)Sd, 1,
                       A1W, A1B, A1U);

    // K6: sentence attention scores + fused final output
    sent_attn_final_kernel<<<Sd, 256>>>(A2W, A2B, A2U, Wf, bf, out);
}